// round 14
// baseline (speedup 1.0000x reference)
#include <cuda_runtime.h>
#include <cuda_fp16.h>
#include <cuda_bf16.h>

#define N_NODES 100000
#define N_EDGES 1600000
#define IN_CH   128
#define NG      16

typedef unsigned long long ull;

// ---------------- scratch (device globals; zero at load, invariant: ---------
// g_aggh/g_deg/g_gsum/g_gcnt are ALL ZERO on entry to every kernel_launch call;
// each call restores them to zero (self-cleaning kernels below).
__device__ __half g_yh  [N_NODES * 64];   // x @ W_l^T  (fp16)
__device__ __half g_xrh [N_NODES * 64];   // x @ W_r^T  (fp16)
__device__ __half g_aggh[N_NODES * 64];   // segment_sum of y over dst (fp16)
__device__ float  g_deg [N_NODES];
__device__ float  g_gsum[NG * 64];
__device__ float  g_gcnt[NG];

// ---------------- kernel (slot 1): node GEMM via tf32 mma.sync ---------------
// [y | xr] = x @ [W_l ; W_r]^T ; both stored fp16.
#define GEMM_BM 128
__device__ __forceinline__ unsigned f2tf32(float f) {
    unsigned u;
    asm("cvt.rna.tf32.f32 %0, %1;" : "=r"(u) : "f"(f));
    return u;
}
__global__ void __launch_bounds__(256, 2) node_gemm(const float* __restrict__ x,
                          const float* __restrict__ Wl,
                          const float* __restrict__ Wr) {
    extern __shared__ unsigned Wsm[];   // [128][132] tf32 bits; Wsm[n][k]

    int tid = threadIdx.x;
    for (int idx = tid; idx < 128 * 128; idx += 256) {
        int n = idx >> 7, k = idx & 127;
        float v = (n < 64) ? Wl[n * 128 + k] : Wr[(n - 64) * 128 + k];
        Wsm[n * 132 + k] = f2tf32(v);
    }
    __syncthreads();

    int w    = tid >> 5;
    int lane = tid & 31;
    int gid  = lane >> 2;
    int tig  = lane & 3;

    int nodeBase = blockIdx.x * GEMM_BM + w * 16;
    int r0 = nodeBase + gid;
    int r1 = r0 + 8;
    int r0c = min(r0, N_NODES - 1);
    int r1c = min(r1, N_NODES - 1);
    const float* xr0 = x + (size_t)r0c * 128;
    const float* xr1 = x + (size_t)r1c * 128;

    float acc[16][4];
#pragma unroll
    for (int nt = 0; nt < 16; nt++)
#pragma unroll
        for (int c = 0; c < 4; c++) acc[nt][c] = 0.f;

#pragma unroll
    for (int ks = 0; ks < 16; ks++) {
        int c0 = ks * 8 + tig;
        unsigned a0 = f2tf32(__ldg(xr0 + c0));
        unsigned a1 = f2tf32(__ldg(xr1 + c0));
        unsigned a2 = f2tf32(__ldg(xr0 + c0 + 4));
        unsigned a3 = f2tf32(__ldg(xr1 + c0 + 4));
#pragma unroll
        for (int nt = 0; nt < 16; nt++) {
            unsigned b0 = Wsm[(nt * 8 + gid) * 132 + ks * 8 + tig];
            unsigned b1 = Wsm[(nt * 8 + gid) * 132 + ks * 8 + tig + 4];
            asm("mma.sync.aligned.m16n8k8.row.col.f32.tf32.tf32.f32 "
                "{%0,%1,%2,%3}, {%4,%5,%6,%7}, {%8,%9}, {%0,%1,%2,%3};"
                : "+f"(acc[nt][0]), "+f"(acc[nt][1]), "+f"(acc[nt][2]), "+f"(acc[nt][3])
                : "r"(a0), "r"(a1), "r"(a2), "r"(a3), "r"(b0), "r"(b1));
        }
    }

#pragma unroll
    for (int nt = 0; nt < 16; nt++) {
        int j = nt * 8 + 2 * tig;          // 0..127, even
        __half2 lo = __floats2half2_rn(acc[nt][0], acc[nt][1]);
        __half2 hi = __floats2half2_rn(acc[nt][2], acc[nt][3]);
        if (j < 64) {
            if (r0 < N_NODES) *reinterpret_cast<__half2*>(&g_yh[(size_t)r0 * 64 + j]) = lo;
            if (r1 < N_NODES) *reinterpret_cast<__half2*>(&g_yh[(size_t)r1 * 64 + j]) = hi;
        } else {
            if (r0 < N_NODES) *reinterpret_cast<__half2*>(&g_xrh[(size_t)r0 * 64 + j - 64]) = lo;
            if (r1 < N_NODES) *reinterpret_cast<__half2*>(&g_xrh[(size_t)r1 * 64 + j - 64]) = hi;
        }
    }
}

// ---------------- kernel (slot 2): edge scatter, fp16 v4.f16x2 reds ----------
__global__ void edge_scatter(const int* __restrict__ ei) {
    int tid = threadIdx.x;
    int e = blockIdx.x * 32 + (tid >> 3);
    int t = tid & 7;
    if (e >= N_EDGES) return;
    int src = __ldg(&ei[e]);
    int dst = __ldg(&ei[N_EDGES + e]);

    const uint4* ysrc = reinterpret_cast<const uint4*>(g_yh + (size_t)src * 64);
    uint4 v = __ldg(ysrc + t);
    __half* dptr = g_aggh + (size_t)dst * 64 + t * 8;
    asm volatile("red.global.add.noftz.v4.f16x2 [%0], {%1, %2, %3, %4};"
                 :: "l"(dptr), "r"(v.x), "r"(v.y), "r"(v.z), "r"(v.w)
                 : "memory");
    if (t == 0) {
        float* dp = g_deg + dst;
        asm volatile("red.global.add.f32 [%0], %1;" :: "l"(dp), "f"(1.0f) : "memory");
    }
}

// ---------------- kernel (slot 3): combine + pool, self-cleaning -------------
// Reads agg/deg, then restores them to ZERO (invariant for next call).
#define POOL_BLOCKS 592
#define POOL_WARPS  (POOL_BLOCKS * 8)
#define POOL_CHUNK  ((N_NODES + POOL_WARPS - 1) / POOL_WARPS)
__global__ void combine_pool(const float* __restrict__ bl,
                             const int* __restrict__ batch) {
    int wid = (blockIdx.x * blockDim.x + threadIdx.x) >> 5;
    int lane = threadIdx.x & 31;
    int start = wid * POOL_CHUNK;
    if (start >= N_NODES) return;
    int end = min(start + POOL_CHUNK, N_NODES);

    float bl0 = bl[2 * lane], bl1 = bl[2 * lane + 1];
    float acc0 = 0.f, acc1 = 0.f, cnt = 0.f;
    int cur = batch[start];

    for (int n = start; n < end; n++) {
        int b = batch[n];
        if (b != cur) {
            atomicAdd(&g_gsum[cur * 64 + 2 * lane], acc0);
            atomicAdd(&g_gsum[cur * 64 + 2 * lane + 1], acc1);
            if (lane == 0) atomicAdd(&g_gcnt[cur], cnt);
            acc0 = acc1 = cnt = 0.f;
            cur = b;
        }
        float dv = g_deg[n];
        float inv = 1.0f / fmaxf(dv, 1.0f);
        __half2* ap = reinterpret_cast<__half2*>(&g_aggh[(size_t)n * 64 + 2 * lane]);
        float2 av = __half22float2(*ap);
        float2 xv = __half22float2(*reinterpret_cast<const __half2*>(&g_xrh[(size_t)n * 64 + 2 * lane]));
        // restore zero invariant (read-once per element; store follows read)
        *ap = __half2half2(__ushort_as_half(0));
        if (lane == 0) g_deg[n] = 0.f;
        float h0 = fmaxf(fmaf(av.x, inv, xv.x + bl0), 0.f);
        float h1 = fmaxf(fmaf(av.y, inv, xv.y + bl1), 0.f);
        acc0 += h0; acc1 += h1; cnt += 1.f;
    }
    atomicAdd(&g_gsum[cur * 64 + 2 * lane], acc0);
    atomicAdd(&g_gsum[cur * 64 + 2 * lane + 1], acc1);
    if (lane == 0) atomicAdd(&g_gcnt[cur], cnt);
}

// ---------------- kernel (slot 4): final MLP, self-cleaning  <-- profiled ----
__global__ void final_mlp(const float* __restrict__ pk, const float* __restrict__ ck,
                          const float* __restrict__ Wp_, const float* __restrict__ bp,
                          const float* __restrict__ Wc, const float* __restrict__ bc,
                          const float* __restrict__ Wh1, const float* __restrict__ bh1,
                          const float* __restrict__ Wh2, const float* __restrict__ bh2,
                          float* __restrict__ out) {
    __shared__ float z[NG][128];
    int w = threadIdx.x >> 5;
    int lane = threadIdx.x & 31;

    float cnt = fmaxf(g_gcnt[w], 1.0f);
    z[w][lane]      = g_gsum[w * 64 + lane] / cnt;
    z[w][lane + 32] = g_gsum[w * 64 + lane + 32] / cnt;
    // restore zero invariant
    g_gsum[w * 64 + lane] = 0.f;
    g_gsum[w * 64 + lane + 32] = 0.f;
    if (lane == 0) g_gcnt[w] = 0.f;

    float s = bp[lane];
#pragma unroll
    for (int k = 0; k < 7; k++) s = fmaf(pk[w * 7 + k], Wp_[lane * 7 + k], s);
    z[w][64 + lane] = fmaxf(s, 0.f);

    s = bc[lane];
#pragma unroll
    for (int k = 0; k < 4; k++) s = fmaf(ck[w * 4 + k], Wc[lane * 4 + k], s);
    z[w][96 + lane] = fmaxf(s, 0.f);
    __syncwarp();

    float a0 = bh1[lane], a1 = bh1[lane + 32];
#pragma unroll 4
    for (int k = 0; k < 128; k++) {
        float zv = z[w][k];
        a0 = fmaf(zv, Wh1[lane * 128 + k], a0);
        a1 = fmaf(zv, Wh1[(lane + 32) * 128 + k], a1);
    }
    a0 = fmaxf(a0, 0.f);
    a1 = fmaxf(a1, 0.f);
    float r = a0 * Wh2[lane] + a1 * Wh2[lane + 32];
#pragma unroll
    for (int off = 16; off > 0; off >>= 1) r += __shfl_down_sync(0xffffffffu, r, off);
    if (lane == 0) out[w] = r + bh2[0];
}

// ---------------- launch -----------------------------------------------------
extern "C" void kernel_launch(void* const* d_in, const int* in_sizes, int n_in,
                              void* d_out, int out_size) {
    const float* x    = (const float*)d_in[0];
    const float* pk   = (const float*)d_in[1];
    const float* ck   = (const float*)d_in[2];
    const float* Wl   = (const float*)d_in[3];
    const float* bl   = (const float*)d_in[4];
    const float* Wr   = (const float*)d_in[5];
    const float* Wp   = (const float*)d_in[6];
    const float* bp   = (const float*)d_in[7];
    const float* Wc   = (const float*)d_in[8];
    const float* bc   = (const float*)d_in[9];
    const float* Wh1  = (const float*)d_in[10];
    const float* bh1  = (const float*)d_in[11];
    const float* Wh2  = (const float*)d_in[12];
    const float* bh2  = (const float*)d_in[13];
    const int*   ei   = (const int*)d_in[14];
    const int*   batch= (const int*)d_in[15];
    float* out = (float*)d_out;

    // slot 1: node GEMM (tf32 tensor cores)
    int gemm_smem = 128 * 132 * 4;
    cudaFuncSetAttribute(node_gemm, cudaFuncAttributeMaxDynamicSharedMemorySize, gemm_smem);
    node_gemm<<<(N_NODES + GEMM_BM - 1) / GEMM_BM, 256, gemm_smem>>>(x, Wl, Wr);

    // slot 2: edge scatter (fp16)
    edge_scatter<<<(N_EDGES + 31) / 32, 256>>>(ei);

    // slot 3: combine + pool (self-cleaning: re-zeros agg/deg)
    combine_pool<<<POOL_BLOCKS, 256>>>(bl, batch);

    // slot 4: final MLP (self-cleaning: re-zeros gsum/gcnt)  <-- profiled
    final_mlp<<<1, 512>>>(pk, ck, Wp, bp, Wc, bc, Wh1, bh1, Wh2, bh2, out);

    (void)in_sizes; (void)n_in; (void)out_size;
}

// round 15
// speedup vs baseline: 2.5216x; 2.5216x over previous
#include <cuda_runtime.h>
#include <cuda_fp16.h>
#include <cuda_bf16.h>

#define N_NODES 100000
#define N_EDGES 1600000
#define IN_CH   128
#define NG      16

typedef unsigned long long ull;

// ---------------- scratch (device globals) ----------------------------------
__device__ __half g_yh  [N_NODES * 64];   // x @ W_l^T  (fp16)
__device__ float  g_xr  [N_NODES * 64];   // x @ W_r^T  (fp32)
__device__ __half g_aggh[N_NODES * 64];   // segment_sum of y over dst (fp16)
__device__ float  g_deg [N_NODES];
__device__ float  g_gsum[NG * 64];
__device__ float  g_gcnt[NG];

// ---------------- kernel (slot 1): zero agg (fp16) + deg ---------------------
__global__ void zero_agg() {
    int i = blockIdx.x * blockDim.x + threadIdx.x;
    int stride = gridDim.x * blockDim.x;
    uint4 z = make_uint4(0u, 0u, 0u, 0u);
    uint4* a4 = reinterpret_cast<uint4*>(g_aggh);
    for (int j = i; j < N_NODES * 8; j += stride) a4[j] = z;   // 12.8 MB
    for (int j = i; j < N_NODES; j += stride) g_deg[j] = 0.f;
}
// ---------------- kernel (slot 3): zero pool accumulators --------------------
__global__ void zero_small() {
    int i = threadIdx.x;
    if (i < NG * 64) g_gsum[i] = 0.f;
    if (i < NG) g_gcnt[i] = 0.f;
}

// ---------------- kernel (slot 2): node GEMM via tf32 mma.sync ---------------
// [y | xr] = x @ [W_l ; W_r]^T ; y stored fp16, xr fp32.
#define GEMM_BM 128
__device__ __forceinline__ unsigned f2tf32(float f) {
    unsigned u;
    asm("cvt.rna.tf32.f32 %0, %1;" : "=r"(u) : "f"(f));
    return u;
}
__global__ void __launch_bounds__(256, 2) node_gemm(const float* __restrict__ x,
                          const float* __restrict__ Wl,
                          const float* __restrict__ Wr) {
    extern __shared__ unsigned Wsm[];   // [128][132] tf32 bits; Wsm[n][k]

    int tid = threadIdx.x;
    for (int idx = tid; idx < 128 * 128; idx += 256) {
        int n = idx >> 7, k = idx & 127;
        float v = (n < 64) ? Wl[n * 128 + k] : Wr[(n - 64) * 128 + k];
        Wsm[n * 132 + k] = f2tf32(v);
    }
    __syncthreads();

    int w    = tid >> 5;
    int lane = tid & 31;
    int gid  = lane >> 2;
    int tig  = lane & 3;

    int nodeBase = blockIdx.x * GEMM_BM + w * 16;
    int r0 = nodeBase + gid;
    int r1 = r0 + 8;
    int r0c = min(r0, N_NODES - 1);
    int r1c = min(r1, N_NODES - 1);
    const float* xr0 = x + (size_t)r0c * 128;
    const float* xr1 = x + (size_t)r1c * 128;

    float acc[16][4];
#pragma unroll
    for (int nt = 0; nt < 16; nt++)
#pragma unroll
        for (int c = 0; c < 4; c++) acc[nt][c] = 0.f;

#pragma unroll
    for (int ks = 0; ks < 16; ks++) {
        int c0 = ks * 8 + tig;
        unsigned a0 = f2tf32(__ldg(xr0 + c0));
        unsigned a1 = f2tf32(__ldg(xr1 + c0));
        unsigned a2 = f2tf32(__ldg(xr0 + c0 + 4));
        unsigned a3 = f2tf32(__ldg(xr1 + c0 + 4));
#pragma unroll
        for (int nt = 0; nt < 16; nt++) {
            unsigned b0 = Wsm[(nt * 8 + gid) * 132 + ks * 8 + tig];
            unsigned b1 = Wsm[(nt * 8 + gid) * 132 + ks * 8 + tig + 4];
            asm("mma.sync.aligned.m16n8k8.row.col.f32.tf32.tf32.f32 "
                "{%0,%1,%2,%3}, {%4,%5,%6,%7}, {%8,%9}, {%0,%1,%2,%3};"
                : "+f"(acc[nt][0]), "+f"(acc[nt][1]), "+f"(acc[nt][2]), "+f"(acc[nt][3])
                : "r"(a0), "r"(a1), "r"(a2), "r"(a3), "r"(b0), "r"(b1));
        }
    }

#pragma unroll
    for (int nt = 0; nt < 16; nt++) {
        int j = nt * 8 + 2 * tig;          // 0..127, even
        if (j < 64) {
            __half2 lo = __floats2half2_rn(acc[nt][0], acc[nt][1]);
            __half2 hi = __floats2half2_rn(acc[nt][2], acc[nt][3]);
            if (r0 < N_NODES) *reinterpret_cast<__half2*>(&g_yh[(size_t)r0 * 64 + j]) = lo;
            if (r1 < N_NODES) *reinterpret_cast<__half2*>(&g_yh[(size_t)r1 * 64 + j]) = hi;
        } else {
            float2 lo = make_float2(acc[nt][0], acc[nt][1]);
            float2 hi = make_float2(acc[nt][2], acc[nt][3]);
            if (r0 < N_NODES) *reinterpret_cast<float2*>(&g_xr[(size_t)r0 * 64 + j - 64]) = lo;
            if (r1 < N_NODES) *reinterpret_cast<float2*>(&g_xr[(size_t)r1 * 64 + j - 64]) = hi;
        }
    }
}

// ---------------- kernel (slot 4): edge scatter, fp16 v4.f16x2 reds ----------
__global__ void edge_scatter(const int* __restrict__ ei) {
    int tid = threadIdx.x;
    int e = blockIdx.x * 32 + (tid >> 3);
    int t = tid & 7;
    if (e >= N_EDGES) return;
    int src = __ldg(&ei[e]);
    int dst = __ldg(&ei[N_EDGES + e]);

    const uint4* ysrc = reinterpret_cast<const uint4*>(g_yh + (size_t)src * 64);
    uint4 v = __ldg(ysrc + t);
    __half* dptr = g_aggh + (size_t)dst * 64 + t * 8;
    asm volatile("red.global.add.noftz.v4.f16x2 [%0], {%1, %2, %3, %4};"
                 :: "l"(dptr), "r"(v.x), "r"(v.y), "r"(v.z), "r"(v.w)
                 : "memory");
    if (t == 0) {
        float* dp = g_deg + dst;
        asm volatile("red.global.add.f32 [%0], %1;" :: "l"(dp), "f"(1.0f) : "memory");
    }
}

// ---------------- kernel (slot 5): combine + per-graph pool ------------------
#define POOL_BLOCKS 592
#define POOL_WARPS  (POOL_BLOCKS * 8)
#define POOL_CHUNK  ((N_NODES + POOL_WARPS - 1) / POOL_WARPS)
__global__ void combine_pool(const float* __restrict__ bl,
                             const int* __restrict__ batch) {
    int wid = (blockIdx.x * blockDim.x + threadIdx.x) >> 5;
    int lane = threadIdx.x & 31;
    int start = wid * POOL_CHUNK;
    if (start >= N_NODES) return;
    int end = min(start + POOL_CHUNK, N_NODES);

    float bl0 = bl[2 * lane], bl1 = bl[2 * lane + 1];
    float acc0 = 0.f, acc1 = 0.f, cnt = 0.f;
    int cur = batch[start];

    for (int n = start; n < end; n++) {
        int b = batch[n];
        if (b != cur) {
            atomicAdd(&g_gsum[cur * 64 + 2 * lane], acc0);
            atomicAdd(&g_gsum[cur * 64 + 2 * lane + 1], acc1);
            if (lane == 0) atomicAdd(&g_gcnt[cur], cnt);
            acc0 = acc1 = cnt = 0.f;
            cur = b;
        }
        float inv = 1.0f / fmaxf(g_deg[n], 1.0f);
        __half2 ah = *reinterpret_cast<const __half2*>(&g_aggh[(size_t)n * 64 + 2 * lane]);
        float2 av = __half22float2(ah);
        float2 xv = *reinterpret_cast<const float2*>(&g_xr[(size_t)n * 64 + 2 * lane]);
        float h0 = fmaxf(fmaf(av.x, inv, xv.x + bl0), 0.f);
        float h1 = fmaxf(fmaf(av.y, inv, xv.y + bl1), 0.f);
        acc0 += h0; acc1 += h1; cnt += 1.f;
    }
    atomicAdd(&g_gsum[cur * 64 + 2 * lane], acc0);
    atomicAdd(&g_gsum[cur * 64 + 2 * lane + 1], acc1);
    if (lane == 0) atomicAdd(&g_gcnt[cur], cnt);
}

// ---------------- kernel (slot 6): final MLP, smem-staged Wh1 ----------------
__global__ void final_mlp(const float* __restrict__ pk, const float* __restrict__ ck,
                          const float* __restrict__ Wp_, const float* __restrict__ bp,
                          const float* __restrict__ Wc, const float* __restrict__ bc,
                          const float* __restrict__ Wh1, const float* __restrict__ bh1,
                          const float* __restrict__ Wh2, const float* __restrict__ bh2,
                          float* __restrict__ out) {
    __shared__ float z[NG][128];
    __shared__ float Wh1s[64][129];   // padded: bank = (row + col) mod 32, conflict-free
    int tid = threadIdx.x;
    int w = tid >> 5;
    int lane = tid & 31;

    // stage Wh1 coalesced (64x128 fp32 = 32KB)
    for (int idx = tid; idx < 64 * 128; idx += 512)
        Wh1s[idx >> 7][idx & 127] = Wh1[idx];

    float cnt = fmaxf(g_gcnt[w], 1.0f);
    z[w][lane]      = g_gsum[w * 64 + lane] / cnt;
    z[w][lane + 32] = g_gsum[w * 64 + lane + 32] / cnt;

    float s = bp[lane];
#pragma unroll
    for (int k = 0; k < 7; k++) s = fmaf(pk[w * 7 + k], Wp_[lane * 7 + k], s);
    z[w][64 + lane] = fmaxf(s, 0.f);

    s = bc[lane];
#pragma unroll
    for (int k = 0; k < 4; k++) s = fmaf(ck[w * 4 + k], Wc[lane * 4 + k], s);
    z[w][96 + lane] = fmaxf(s, 0.f);
    __syncthreads();

    float a0 = bh1[lane], a1 = bh1[lane + 32];
#pragma unroll 8
    for (int k = 0; k < 128; k++) {
        float zv = z[w][k];
        a0 = fmaf(zv, Wh1s[lane][k], a0);
        a1 = fmaf(zv, Wh1s[lane + 32][k], a1);
    }
    a0 = fmaxf(a0, 0.f);
    a1 = fmaxf(a1, 0.f);
    float r = a0 * Wh2[lane] + a1 * Wh2[lane + 32];
#pragma unroll
    for (int off = 16; off > 0; off >>= 1) r += __shfl_down_sync(0xffffffffu, r, off);
    if (lane == 0) out[w] = r + bh2[0];
}

// ---------------- launch -----------------------------------------------------
extern "C" void kernel_launch(void* const* d_in, const int* in_sizes, int n_in,
                              void* d_out, int out_size) {
    const float* x    = (const float*)d_in[0];
    const float* pk   = (const float*)d_in[1];
    const float* ck   = (const float*)d_in[2];
    const float* Wl   = (const float*)d_in[3];
    const float* bl   = (const float*)d_in[4];
    const float* Wr   = (const float*)d_in[5];
    const float* Wp   = (const float*)d_in[6];
    const float* bp   = (const float*)d_in[7];
    const float* Wc   = (const float*)d_in[8];
    const float* bc   = (const float*)d_in[9];
    const float* Wh1  = (const float*)d_in[10];
    const float* bh1  = (const float*)d_in[11];
    const float* Wh2  = (const float*)d_in[12];
    const float* bh2  = (const float*)d_in[13];
    const int*   ei   = (const int*)d_in[14];
    const int*   batch= (const int*)d_in[15];
    float* out = (float*)d_out;

    // slot 1: zero agg (fp16) + deg
    zero_agg<<<1024, 256>>>();

    // slot 2: node GEMM (tf32 tensor cores)
    int gemm_smem = 128 * 132 * 4;
    cudaFuncSetAttribute(node_gemm, cudaFuncAttributeMaxDynamicSharedMemorySize, gemm_smem);
    node_gemm<<<(N_NODES + GEMM_BM - 1) / GEMM_BM, 256, gemm_smem>>>(x, Wl, Wr);

    // slot 3: tiny zero
    zero_small<<<1, 1024>>>();

    // slot 4: edge scatter (fp16)  <-- profiled
    edge_scatter<<<(N_EDGES + 31) / 32, 256>>>(ei);

    // slot 5: combine + pool
    combine_pool<<<POOL_BLOCKS, 256>>>(bl, batch);

    // slot 6: final MLP (smem-staged Wh1)
    final_mlp<<<1, 512>>>(pk, ck, Wp, bp, Wc, bc, Wh1, bh1, Wh2, bh2, out);

    (void)in_sizes; (void)n_in; (void)out_size;
}

// round 17
// speedup vs baseline: 2.7307x; 1.0829x over previous
#include <cuda_runtime.h>
#include <cuda_fp16.h>
#include <cuda_bf16.h>

#define N_NODES 100000
#define N_EDGES 1600000
#define IN_CH   128
#define NG      16

typedef unsigned long long ull;

// ---------------- scratch (device globals) ----------------------------------
__device__ __half g_yh  [N_NODES * 64];   // x @ W_l^T  (fp16)
__device__ float  g_xr  [N_NODES * 64];   // x @ W_r^T  (fp32)
__device__ __half g_aggh[N_NODES * 64];   // segment_sum of y over dst (fp16)
__device__ float  g_deg [N_NODES];
__device__ float  g_gsum[NG * 64];
__device__ float  g_gcnt[NG];

// ---------------- kernel (slot 1): zero agg (fp16) + deg ---------------------
__global__ void zero_agg() {
    int i = blockIdx.x * blockDim.x + threadIdx.x;
    int stride = gridDim.x * blockDim.x;
    uint4 z = make_uint4(0u, 0u, 0u, 0u);
    uint4* a4 = reinterpret_cast<uint4*>(g_aggh);
    for (int j = i; j < N_NODES * 8; j += stride) a4[j] = z;   // 12.8 MB
    for (int j = i; j < N_NODES; j += stride) g_deg[j] = 0.f;
}
// ---------------- kernel (slot 3): zero pool accumulators --------------------
__global__ void zero_small() {
    int i = threadIdx.x;
    if (i < NG * 64) g_gsum[i] = 0.f;
    if (i < NG) g_gcnt[i] = 0.f;
}

// ---------------- kernel (slot 2): node GEMM via fp16 m16n8k16 mma -----------
// [y | xr] = x @ [W_l ; W_r]^T ; y stored fp16, xr fp32. fp32 accumulate.
// W staged as two half2 arrays W0/W1[kp][c], row stride 136 words -> the
// per-fragment access (tig,gid) hits 8*tig+gid: all 32 lanes distinct banks.
#define GEMM_BM 128
__device__ __forceinline__ unsigned packh2(float lo, float hi) {
    __half2 h = __floats2half2_rn(lo, hi);
    return *reinterpret_cast<unsigned*>(&h);
}
__global__ void __launch_bounds__(256, 2) node_gemm(const float* __restrict__ x,
                          const float* __restrict__ Wl,
                          const float* __restrict__ Wr) {
    extern __shared__ unsigned smemw[];
    unsigned* W0 = smemw;               // [32][136]  (kp = ks*4+tig, c)
    unsigned* W1 = smemw + 32 * 136;    // [32][136]

    int tid = threadIdx.x;
    for (int idx = tid; idx < 128 * 32; idx += 256) {
        int c = idx >> 5, kp = idx & 31;
        int ks = kp >> 2, tg = kp & 3;
        int k0 = ks * 16 + 2 * tg;
        const float* wrow = (c < 64) ? (Wl + c * 128) : (Wr + (c - 64) * 128);
        W0[kp * 136 + c] = packh2(wrow[k0],     wrow[k0 + 1]);
        W1[kp * 136 + c] = packh2(wrow[k0 + 8], wrow[k0 + 9]);
    }
    __syncthreads();

    int w    = tid >> 5;
    int lane = tid & 31;
    int gid  = lane >> 2;
    int tig  = lane & 3;

    int nodeBase = blockIdx.x * GEMM_BM + w * 16;
    int r0 = nodeBase + gid;
    int r1 = r0 + 8;
    int r0c = min(r0, N_NODES - 1);
    int r1c = min(r1, N_NODES - 1);
    const float* xr0 = x + (size_t)r0c * 128;
    const float* xr1 = x + (size_t)r1c * 128;

    float acc[16][4];
#pragma unroll
    for (int nt = 0; nt < 16; nt++)
#pragma unroll
        for (int c = 0; c < 4; c++) acc[nt][c] = 0.f;

#pragma unroll
    for (int ks = 0; ks < 8; ks++) {
        int kb = ks * 16 + 2 * tig;
        float2 p0 = *reinterpret_cast<const float2*>(xr0 + kb);
        float2 p1 = *reinterpret_cast<const float2*>(xr1 + kb);
        float2 p2 = *reinterpret_cast<const float2*>(xr0 + kb + 8);
        float2 p3 = *reinterpret_cast<const float2*>(xr1 + kb + 8);
        unsigned a0 = packh2(p0.x, p0.y);
        unsigned a1 = packh2(p1.x, p1.y);
        unsigned a2 = packh2(p2.x, p2.y);
        unsigned a3 = packh2(p3.x, p3.y);
        int kpbase = (ks * 4 + tig) * 136 + gid;
#pragma unroll
        for (int nt = 0; nt < 16; nt++) {
            unsigned b0 = W0[kpbase + nt * 8];
            unsigned b1 = W1[kpbase + nt * 8];
            asm("mma.sync.aligned.m16n8k16.row.col.f32.f16.f16.f32 "
                "{%0,%1,%2,%3}, {%4,%5,%6,%7}, {%8,%9}, {%0,%1,%2,%3};"
                : "+f"(acc[nt][0]), "+f"(acc[nt][1]), "+f"(acc[nt][2]), "+f"(acc[nt][3])
                : "r"(a0), "r"(a1), "r"(a2), "r"(a3), "r"(b0), "r"(b1));
        }
    }

#pragma unroll
    for (int nt = 0; nt < 16; nt++) {
        int j = nt * 8 + 2 * tig;          // 0..127, even
        if (j < 64) {
            __half2 lo = __floats2half2_rn(acc[nt][0], acc[nt][1]);
            __half2 hi = __floats2half2_rn(acc[nt][2], acc[nt][3]);
            if (r0 < N_NODES) *reinterpret_cast<__half2*>(&g_yh[(size_t)r0 * 64 + j]) = lo;
            if (r1 < N_NODES) *reinterpret_cast<__half2*>(&g_yh[(size_t)r1 * 64 + j]) = hi;
        } else {
            float2 lo = make_float2(acc[nt][0], acc[nt][1]);
            float2 hi = make_float2(acc[nt][2], acc[nt][3]);
            if (r0 < N_NODES) *reinterpret_cast<float2*>(&g_xr[(size_t)r0 * 64 + j - 64]) = lo;
            if (r1 < N_NODES) *reinterpret_cast<float2*>(&g_xr[(size_t)r1 * 64 + j - 64]) = hi;
        }
    }
}

// ---------------- kernel (slot 4): edge scatter, fp16 v4.f16x2 reds ----------
__global__ void edge_scatter(const int* __restrict__ ei) {
    int tid = threadIdx.x;
    int e = blockIdx.x * 32 + (tid >> 3);
    int t = tid & 7;
    if (e >= N_EDGES) return;
    int src = __ldg(&ei[e]);
    int dst = __ldg(&ei[N_EDGES + e]);

    const uint4* ysrc = reinterpret_cast<const uint4*>(g_yh + (size_t)src * 64);
    uint4 v = __ldg(ysrc + t);
    __half* dptr = g_aggh + (size_t)dst * 64 + t * 8;
    asm volatile("red.global.add.noftz.v4.f16x2 [%0], {%1, %2, %3, %4};"
                 :: "l"(dptr), "r"(v.x), "r"(v.y), "r"(v.z), "r"(v.w)
                 : "memory");
    if (t == 0) {
        float* dp = g_deg + dst;
        asm volatile("red.global.add.f32 [%0], %1;" :: "l"(dp), "f"(1.0f) : "memory");
    }
}

// ---------------- kernel (slot 5): combine + per-graph pool ------------------
#define POOL_BLOCKS 592
#define POOL_WARPS  (POOL_BLOCKS * 8)
#define POOL_CHUNK  ((N_NODES + POOL_WARPS - 1) / POOL_WARPS)
__global__ void combine_pool(const float* __restrict__ bl,
                             const int* __restrict__ batch) {
    int wid = (blockIdx.x * blockDim.x + threadIdx.x) >> 5;
    int lane = threadIdx.x & 31;
    int start = wid * POOL_CHUNK;
    if (start >= N_NODES) return;
    int end = min(start + POOL_CHUNK, N_NODES);

    float bl0 = bl[2 * lane], bl1 = bl[2 * lane + 1];
    float acc0 = 0.f, acc1 = 0.f, cnt = 0.f;
    int cur = batch[start];

    for (int n = start; n < end; n++) {
        int b = batch[n];
        if (b != cur) {
            atomicAdd(&g_gsum[cur * 64 + 2 * lane], acc0);
            atomicAdd(&g_gsum[cur * 64 + 2 * lane + 1], acc1);
            if (lane == 0) atomicAdd(&g_gcnt[cur], cnt);
            acc0 = acc1 = cnt = 0.f;
            cur = b;
        }
        float inv = 1.0f / fmaxf(g_deg[n], 1.0f);
        __half2 ah = *reinterpret_cast<const __half2*>(&g_aggh[(size_t)n * 64 + 2 * lane]);
        float2 av = __half22float2(ah);
        float2 xv = *reinterpret_cast<const float2*>(&g_xr[(size_t)n * 64 + 2 * lane]);
        float h0 = fmaxf(fmaf(av.x, inv, xv.x + bl0), 0.f);
        float h1 = fmaxf(fmaf(av.y, inv, xv.y + bl1), 0.f);
        acc0 += h0; acc1 += h1; cnt += 1.f;
    }
    atomicAdd(&g_gsum[cur * 64 + 2 * lane], acc0);
    atomicAdd(&g_gsum[cur * 64 + 2 * lane + 1], acc1);
    if (lane == 0) atomicAdd(&g_gcnt[cur], cnt);
}

// ---------------- kernel (slot 6): final MLP, smem-staged Wh1 ----------------
__global__ void final_mlp(const float* __restrict__ pk, const float* __restrict__ ck,
                          const float* __restrict__ Wp_, const float* __restrict__ bp,
                          const float* __restrict__ Wc, const float* __restrict__ bc,
                          const float* __restrict__ Wh1, const float* __restrict__ bh1,
                          const float* __restrict__ Wh2, const float* __restrict__ bh2,
                          float* __restrict__ out) {
    __shared__ float z[NG][128];
    __shared__ float Wh1s[64][129];
    int tid = threadIdx.x;
    int w = tid >> 5;
    int lane = tid & 31;

    for (int idx = tid; idx < 64 * 128; idx += 512)
        Wh1s[idx >> 7][idx & 127] = Wh1[idx];

    float cnt = fmaxf(g_gcnt[w], 1.0f);
    z[w][lane]      = g_gsum[w * 64 + lane] / cnt;
    z[w][lane + 32] = g_gsum[w * 64 + lane + 32] / cnt;

    float s = bp[lane];
#pragma unroll
    for (int k = 0; k < 7; k++) s = fmaf(pk[w * 7 + k], Wp_[lane * 7 + k], s);
    z[w][64 + lane] = fmaxf(s, 0.f);

    s = bc[lane];
#pragma unroll
    for (int k = 0; k < 4; k++) s = fmaf(ck[w * 4 + k], Wc[lane * 4 + k], s);
    z[w][96 + lane] = fmaxf(s, 0.f);
    __syncthreads();

    float a0 = bh1[lane], a1 = bh1[lane + 32];
#pragma unroll 8
    for (int k = 0; k < 128; k++) {
        float zv = z[w][k];
        a0 = fmaf(zv, Wh1s[lane][k], a0);
        a1 = fmaf(zv, Wh1s[lane + 32][k], a1);
    }
    a0 = fmaxf(a0, 0.f);
    a1 = fmaxf(a1, 0.f);
    float r = a0 * Wh2[lane] + a1 * Wh2[lane + 32];
#pragma unroll
    for (int off = 16; off > 0; off >>= 1) r += __shfl_down_sync(0xffffffffu, r, off);
    if (lane == 0) out[w] = r + bh2[0];
}

// ---------------- launch -----------------------------------------------------
extern "C" void kernel_launch(void* const* d_in, const int* in_sizes, int n_in,
                              void* d_out, int out_size) {
    const float* x    = (const float*)d_in[0];
    const float* pk   = (const float*)d_in[1];
    const float* ck   = (const float*)d_in[2];
    const float* Wl   = (const float*)d_in[3];
    const float* bl   = (const float*)d_in[4];
    const float* Wr   = (const float*)d_in[5];
    const float* Wp   = (const float*)d_in[6];
    const float* bp   = (const float*)d_in[7];
    const float* Wc   = (const float*)d_in[8];
    const float* bc   = (const float*)d_in[9];
    const float* Wh1  = (const float*)d_in[10];
    const float* bh1  = (const float*)d_in[11];
    const float* Wh2  = (const float*)d_in[12];
    const float* bh2  = (const float*)d_in[13];
    const int*   ei   = (const int*)d_in[14];
    const int*   batch= (const int*)d_in[15];
    float* out = (float*)d_out;

    // slot 1: zero agg (fp16) + deg
    zero_agg<<<1024, 256>>>();

    // slot 2: node GEMM (fp16 tensor cores)
    int gemm_smem = 2 * 32 * 136 * 4;   // 34816 bytes
    cudaFuncSetAttribute(node_gemm, cudaFuncAttributeMaxDynamicSharedMemorySize, gemm_smem);
    node_gemm<<<(N_NODES + GEMM_BM - 1) / GEMM_BM, 256, gemm_smem>>>(x, Wl, Wr);

    // slot 3: tiny zero
    zero_small<<<1, 1024>>>();

    // slot 4: edge scatter (fp16)  <-- profiled
    edge_scatter<<<(N_EDGES + 31) / 32, 256>>>(ei);

    // slot 5: combine + pool
    combine_pool<<<POOL_BLOCKS, 256>>>(bl, batch);

    // slot 6: final MLP (smem-staged Wh1)
    final_mlp<<<1, 512>>>(pk, ck, Wp, bp, Wc, bc, Wh1, bh1, Wh2, bh2, out);

    (void)in_sizes; (void)n_in; (void)out_size;
}